// round 6
// baseline (speedup 1.0000x reference)
#include <cuda_runtime.h>
#include <cuda_bf16.h>
#include <math.h>

// ---------------------------------------------------------------------------
// CfC recurrence, persistent weight-stationary kernel.
// B=64, T=1024, D=256, H=512, BU=512, Z=D+H=768.
// Grid: 128 CTAs x 256 threads. CTA i owns output columns [4i, 4i+4) of all
// five weight matrices (held in SMEM). Thread t owns (b = t>>2, c = t&3):
// one bb element in phase A, one (ff1,ff2,ta,tb,h,s) element in phase B.
// Two global sense-reversing barriers per timestep.
// Cross-CTA activations (g_h, g_bb) move exclusively through L2 via
// cp.async.cg (loads) and write-through global stores + __threadfence.
// ---------------------------------------------------------------------------

#define Bc   64
#define Tc   1024
#define Dc   256
#define Hc   512
#define ZC   768
#define NCTA 128
#define NTHR 256
#define CPC  4          // columns per CTA
#define KCH  256        // K chunk staged per buffer
#define ZPAD 260        // stage row stride (floats): 260 % 32 == 4 -> conflict-free
#define WBBP 772        // Wbb column stride (768 + 4 pad)
#define W4P  516        // Wff*/Wt* column stride (512 + 4 pad)
#define STGF (64 * ZPAD)                    // floats per stage buffer
#define SMEM_FLOATS (CPC*WBBP + 16*W4P + 2*STGF)
#define SMEM_BYTES  (SMEM_FLOATS * 4)

// -------------------- device-global state (static, no allocation) ----------
__device__ unsigned g_count = 0;
__device__ unsigned g_sense = 0;
__device__ __align__(256) float g_h[Bc * Hc];
__device__ __align__(256) float g_bb[Bc * Hc];

// ------------------------------- helpers -----------------------------------
__device__ __forceinline__ void cp16(float* dst_smem, const float* src_gmem) {
    unsigned d = (unsigned)__cvta_generic_to_shared(dst_smem);
    asm volatile("cp.async.cg.shared.global [%0], [%1], 16;"
                 :: "r"(d), "l"(src_gmem) : "memory");
}
__device__ __forceinline__ void cp_commit() {
    asm volatile("cp.async.commit_group;" ::: "memory");
}
template <int N>
__device__ __forceinline__ void cp_wait() {
    asm volatile("cp.async.wait_group %0;" :: "n"(N) : "memory");
}

// Global barrier: sense-reversing epoch counter. Only thread 0 of each CTA
// touches the flag; target = initial sense + epoch (wraparound-safe equality).
__device__ __forceinline__ void gbar(unsigned sense0, unsigned& ep) {
    __syncthreads();
    ep++;
    if (threadIdx.x == 0) {
        unsigned target = sense0 + ep;
        __threadfence();  // release: prior global writes visible at L2
        if (atomicAdd(&g_count, 1u) == (unsigned)(NCTA - 1)) {
            atomicExch(&g_count, 0u);
            asm volatile("st.release.gpu.u32 [%0], %1;"
                         :: "l"(&g_sense), "r"(target) : "memory");
        } else {
            unsigned v;
            do {
                asm volatile("ld.acquire.gpu.u32 %0, [%1];"
                             : "=r"(v) : "l"(&g_sense) : "memory");
            } while (v != target);
        }
    }
    __syncthreads();
}

// Stage one K-chunk of z = [x_t | h] into a SMEM buffer. kb in {0,256,512}.
__device__ __forceinline__ void stageA(float* buf, const float* __restrict__ x,
                                       int t, int kb) {
    int tid = threadIdx.x;
#pragma unroll
    for (int i = 0; i < 16; i++) {
        int lin = tid + i * NTHR;        // 0..4095
        int b   = lin >> 6;              // 0..63
        int j   = (lin & 63) * 4;        // 0..252 (float4 column)
        const float* src = (kb == 0)
            ? (x + ((size_t)(b * Tc + t)) * Dc + j)
            : (g_h + b * Hc + (kb - Dc) + j);
        cp16(buf + b * ZPAD + j, src);
    }
    cp_commit();
}

// Stage one K-chunk of bb into a SMEM buffer. kb in {0,256}.
__device__ __forceinline__ void stageB(float* buf, int kb) {
    int tid = threadIdx.x;
#pragma unroll
    for (int i = 0; i < 16; i++) {
        int lin = tid + i * NTHR;
        int b   = lin >> 6;
        int j   = (lin & 63) * 4;
        cp16(buf + b * ZPAD + j, g_bb + b * Hc + kb + j);
    }
    cp_commit();
}

// Phase A partial GEMM over one K-chunk: acc[0..3] are k-phase accumulators.
__device__ __forceinline__ void gemmA(const float* __restrict__ zrow,
                                      const float* __restrict__ wcol,
                                      float acc[4]) {
#pragma unroll 8
    for (int k4 = 0; k4 < KCH / 4; k4++) {
        float4 z = *(const float4*)(zrow + 4 * k4);
        float4 w = *(const float4*)(wcol + 4 * k4);
        acc[0] = fmaf(z.x, w.x, acc[0]);
        acc[1] = fmaf(z.y, w.y, acc[1]);
        acc[2] = fmaf(z.z, w.z, acc[2]);
        acc[3] = fmaf(z.w, w.w, acc[3]);
    }
}

// Phase B partial GEMM over one K-chunk: 4 matrices, component accumulators.
__device__ __forceinline__ void gemmB(const float* __restrict__ zrow,
                                      const float* __restrict__ w1,
                                      const float* __restrict__ w2,
                                      const float* __restrict__ w3,
                                      const float* __restrict__ w4,
                                      float4& f1, float4& f2,
                                      float4& f3, float4& f4) {
#pragma unroll 4
    for (int k4 = 0; k4 < KCH / 4; k4++) {
        float4 z = *(const float4*)(zrow + 4 * k4);
        float4 a = *(const float4*)(w1 + 4 * k4);
        f1.x = fmaf(z.x, a.x, f1.x); f1.y = fmaf(z.y, a.y, f1.y);
        f1.z = fmaf(z.z, a.z, f1.z); f1.w = fmaf(z.w, a.w, f1.w);
        float4 bq = *(const float4*)(w2 + 4 * k4);
        f2.x = fmaf(z.x, bq.x, f2.x); f2.y = fmaf(z.y, bq.y, f2.y);
        f2.z = fmaf(z.z, bq.z, f2.z); f2.w = fmaf(z.w, bq.w, f2.w);
        float4 cq = *(const float4*)(w3 + 4 * k4);
        f3.x = fmaf(z.x, cq.x, f3.x); f3.y = fmaf(z.y, cq.y, f3.y);
        f3.z = fmaf(z.z, cq.z, f3.z); f3.w = fmaf(z.w, cq.w, f3.w);
        float4 dq = *(const float4*)(w4 + 4 * k4);
        f4.x = fmaf(z.x, dq.x, f4.x); f4.y = fmaf(z.y, dq.y, f4.y);
        f4.z = fmaf(z.z, dq.z, f4.z); f4.w = fmaf(z.w, dq.w, f4.w);
    }
}

// --------------------------------- kernel ----------------------------------
__global__ void __launch_bounds__(NTHR, 1)
cfc_persistent_kernel(const float* __restrict__ x,   const float* __restrict__ ts,
                      const float* __restrict__ h0,  const float* __restrict__ s0,
                      const float* __restrict__ Wbb, const float* __restrict__ bbb,
                      const float* __restrict__ Wff1,const float* __restrict__ bff1,
                      const float* __restrict__ Wff2,const float* __restrict__ bff2,
                      const float* __restrict__ Wta, const float* __restrict__ bta,
                      const float* __restrict__ Wtb, const float* __restrict__ btb,
                      float* __restrict__ out) {
    extern __shared__ float smem[];
    float* s_wbb = smem;                        // [4][772]
    float* s_w4  = s_wbb + CPC * WBBP;          // [4 matrices][4 cols][516]
    float* s_stg = s_w4  + 16 * W4P;            // [2][64][260]

    const int tid = threadIdx.x;
    const int c   = tid & 3;
    const int b   = tid >> 2;
    const int c0  = blockIdx.x * CPC;
    const int cg  = c0 + c;

    // ---- one-time: weights column slice -> SMEM (column-major, padded) ----
    for (int idx = tid; idx < ZC * CPC; idx += NTHR) {
        int k = idx >> 2, cc = idx & 3;
        s_wbb[cc * WBBP + k] = __ldg(Wbb + (size_t)k * Hc + c0 + cc);
    }
    {
        const float* Wm[4] = {Wff1, Wff2, Wta, Wtb};
#pragma unroll
        for (int m = 0; m < 4; m++) {
            for (int idx = tid; idx < Hc * CPC; idx += NTHR) {
                int k = idx >> 2, cc = idx & 3;
                s_w4[(m * 4 + cc) * W4P + k] = __ldg(Wm[m] + (size_t)k * Hc + c0 + cc);
            }
        }
    }
    const float bbbc = __ldg(bbb  + cg);
    const float bf1c = __ldg(bff1 + cg);
    const float bf2c = __ldg(bff2 + cg);
    const float btac = __ldg(bta  + cg);
    const float btbc = __ldg(btb  + cg);

    // ---- persistent per-thread state ----
    float s_state = __ldg(s0 + b * Hc + cg);
    g_h[b * Hc + cg] = __ldg(h0 + b * Hc + cg);

    unsigned sense0 = 0, ep = 0;
    if (tid == 0) {
        asm volatile("ld.acquire.gpu.u32 %0, [%1];"
                     : "=r"(sense0) : "l"(&g_sense) : "memory");
    }
    gbar(sense0, ep);   // h0 visible chip-wide

    float* buf0 = s_stg;
    float* buf1 = s_stg + STGF;
    const float* w1p = s_w4 + (0 * 4 + c) * W4P;
    const float* w2p = s_w4 + (1 * 4 + c) * W4P;
    const float* w3p = s_w4 + (2 * 4 + c) * W4P;
    const float* w4p = s_w4 + (3 * 4 + c) * W4P;
    const float* wbp = s_wbb + c * WBBP;
    const int rofs = b * ZPAD;

    for (int t = 0; t < Tc; t++) {
        // ================= Phase A: bb = silu(z @ Wbb + bbb) =================
        float a[4] = {0.f, 0.f, 0.f, 0.f};
        stageA(buf0, x, t, 0);       // G0: x chunk
        stageA(buf1, x, t, 256);     // G1: h[0:256]
        cp_wait<1>(); __syncthreads();
        gemmA(buf0 + rofs, wbp + 0, a);
        __syncthreads();
        stageA(buf0, x, t, 512);     // G2: h[256:512]
        cp_wait<1>(); __syncthreads();
        gemmA(buf1 + rofs, wbp + 256, a);
        __syncthreads();
        cp_wait<0>(); __syncthreads();
        gemmA(buf0 + rofs, wbp + 512, a);

        float av  = a[0] + a[1] + a[2] + a[3] + bbbc;
        float bbv = av / (1.0f + expf(-av));          // silu
        g_bb[b * Hc + cg] = bbv;
        gbar(sense0, ep);

        // ========== Phase B: ff1/ff2/ta/tb = bb @ W* ; gate & update ==========
        float4 f1 = {0.f,0.f,0.f,0.f}, f2 = {0.f,0.f,0.f,0.f};
        float4 f3 = {0.f,0.f,0.f,0.f}, f4 = {0.f,0.f,0.f,0.f};
        stageB(buf0, 0);             // G0': bb[0:256]
        stageB(buf1, 256);           // G1': bb[256:512]
        cp_wait<1>(); __syncthreads();
        gemmB(buf0 + rofs, w1p, w2p, w3p, w4p, f1, f2, f3, f4);
        cp_wait<0>(); __syncthreads();
        gemmB(buf1 + rofs, w1p + 256, w2p + 256, w3p + 256, w4p + 256,
              f1, f2, f3, f4);

        float ff1 = tanhf(f1.x + f1.y + f1.z + f1.w + bf1c);
        float ff2 = tanhf(f2.x + f2.y + f2.z + f2.w + bf2c);
        float tstv = __ldg(ts + b * Tc + t);
        float tn   = 1.0f / tstv;
        float wts  = (tn > 0.0f) ? expf(tn * (1.0f - 2.0f * logf(tn))) : 0.0f;
        float tsum = (f3.x + f3.y + f3.z + f3.w + btac) * wts
                   + (f4.x + f4.y + f4.z + f4.w + btbc);
        s_state += tsum;
        float ti = 1.0f / (1.0f + expf(-s_state));
        float hn = ff1 + ti * (ff2 - ff1);

        g_h[b * Hc + cg] = hn;
        out[((size_t)b * Tc + t) * Hc + cg] = hn;
        gbar(sense0, ep);
    }
}

// --------------------------------- launch ----------------------------------
extern "C" void kernel_launch(void* const* d_in, const int* in_sizes, int n_in,
                              void* d_out, int out_size) {
    (void)in_sizes; (void)n_in; (void)out_size;
    cudaFuncSetAttribute(cfc_persistent_kernel,
                         cudaFuncAttributeMaxDynamicSharedMemorySize, SMEM_BYTES);
    cfc_persistent_kernel<<<NCTA, NTHR, SMEM_BYTES>>>(
        (const float*)d_in[0],  (const float*)d_in[1],
        (const float*)d_in[2],  (const float*)d_in[3],
        (const float*)d_in[4],  (const float*)d_in[5],
        (const float*)d_in[6],  (const float*)d_in[7],
        (const float*)d_in[8],  (const float*)d_in[9],
        (const float*)d_in[10], (const float*)d_in[11],
        (const float*)d_in[12], (const float*)d_in[13],
        (float*)d_out);
}

// round 7
// speedup vs baseline: 1.0205x; 1.0205x over previous
#include <cuda_runtime.h>
#include <cuda_bf16.h>
#include <math.h>

// ---------------------------------------------------------------------------
// CfC recurrence, persistent weight-stationary kernel. v2:
//   - 512 threads/CTA (16 warps), K split in half per thread + SMEM reduction
//   - packed fma.rn.f32x2 (FFMA2) inner loops
//   - split global barrier (arrive / wait) with x-staging + ts-math hidden
//     under the barrier spin
// B=64, T=1024, D=256, H=512, BU=512, Z=768. 128 CTAs x 4 columns each.
// ---------------------------------------------------------------------------

#define Bc   64
#define Tc   1024
#define Dc   256
#define Hc   512
#define ZC   768
#define NCTA 128
#define NTHR 512
#define CPC  4          // columns per CTA
#define KCH  256        // staged K chunk
#define KH   128        // K per khalf within a chunk
#define ZPAD 260        // stage row stride: 260 % 32 == 4 -> conflict-free
#define WBBP 772
#define W4P  516
#define STGF (64 * ZPAD)
#define SMEM_FLOATS (CPC*WBBP + 16*W4P + 2*STGF + 256 + 256*5)
#define SMEM_BYTES  (SMEM_FLOATS * 4)

// -------------------- device-global state ----------------------------------
__device__ unsigned g_count = 0;
__device__ unsigned g_sense = 0;
__device__ __align__(256) float g_h[Bc * Hc];
__device__ __align__(256) float g_bb[Bc * Hc];

// ------------------------------- helpers -----------------------------------
__device__ __forceinline__ void cp16(float* dst_smem, const float* src_gmem) {
    unsigned d = (unsigned)__cvta_generic_to_shared(dst_smem);
    asm volatile("cp.async.cg.shared.global [%0], [%1], 16;"
                 :: "r"(d), "l"(src_gmem) : "memory");
}
__device__ __forceinline__ void cp_commit() {
    asm volatile("cp.async.commit_group;" ::: "memory");
}
template <int N>
__device__ __forceinline__ void cp_wait() {
    asm volatile("cp.async.wait_group %0;" :: "n"(N) : "memory");
}

// packed dual-FMA (B300 FFMA2): d.lo += a.lo*b.lo ; d.hi += a.hi*b.hi
__device__ __forceinline__ void ffma2(unsigned long long& d,
                                      unsigned long long a,
                                      unsigned long long b) {
    asm("fma.rn.f32x2 %0, %1, %2, %0;" : "+l"(d) : "l"(a), "l"(b));
}
__device__ __forceinline__ float hsum2(unsigned long long v) {
    return __uint_as_float((unsigned)v) + __uint_as_float((unsigned)(v >> 32));
}

// ---- split global barrier (sense-reversing epoch) ----
__device__ __forceinline__ void gbar_arrive(unsigned sense0, unsigned& ep) {
    __syncthreads();                 // all prior work (incl. global stores) done
    ep++;
    if (threadIdx.x == 0) {
        __threadfence();             // release stores to L2
        if (atomicAdd(&g_count, 1u) == (unsigned)(NCTA - 1)) {
            atomicExch(&g_count, 0u);
            asm volatile("st.release.gpu.u32 [%0], %1;"
                         :: "l"(&g_sense), "r"(sense0 + ep) : "memory");
        }
    }
}
__device__ __forceinline__ void gbar_wait(unsigned sense0, unsigned ep) {
    if (threadIdx.x == 0) {
        unsigned v, target = sense0 + ep;
        do {
            asm volatile("ld.acquire.gpu.u32 %0, [%1];"
                         : "=r"(v) : "l"(&g_sense) : "memory");
        } while (v != target);
    }
    __syncthreads();
}

// Stage one K-chunk of z = [x_t | h]. kb in {0,256,512}. 8 cp.async/thread.
__device__ __forceinline__ void stageA(float* buf, const float* __restrict__ x,
                                       int t, int kb) {
    int tid = threadIdx.x;
#pragma unroll
    for (int i = 0; i < 8; i++) {
        int lin = tid + i * NTHR;        // 0..4095
        int b   = lin >> 6;
        int j   = (lin & 63) * 4;
        const float* src = (kb == 0)
            ? (x + ((size_t)(b * Tc + t)) * Dc + j)
            : (g_h + b * Hc + (kb - Dc) + j);
        cp16(buf + b * ZPAD + j, src);
    }
    cp_commit();
}
__device__ __forceinline__ void stageB(float* buf, int kb) {
    int tid = threadIdx.x;
#pragma unroll
    for (int i = 0; i < 8; i++) {
        int lin = tid + i * NTHR;
        int b   = lin >> 6;
        int j   = (lin & 63) * 4;
        cp16(buf + b * ZPAD + j, g_bb + b * Hc + kb + j);
    }
    cp_commit();
}

// Phase A partial over one khalf (KH=128 values): 2 packed accumulators.
__device__ __forceinline__ void gemmA(const float* __restrict__ zrow,
                                      const float* __restrict__ wcol,
                                      unsigned long long& a0,
                                      unsigned long long& a1) {
#pragma unroll 8
    for (int k4 = 0; k4 < KH / 4; k4++) {
        ulonglong2 z = *(const ulonglong2*)(zrow + 4 * k4);
        ulonglong2 w = *(const ulonglong2*)(wcol + 4 * k4);
        ffma2(a0, z.x, w.x);
        ffma2(a1, z.y, w.y);
    }
}

// Phase B partial over one khalf: 4 matrices, 8 packed accumulators.
__device__ __forceinline__ void gemmB(const float* __restrict__ zrow,
                                      const float* __restrict__ w1,
                                      const float* __restrict__ w2,
                                      const float* __restrict__ w3,
                                      const float* __restrict__ w4,
                                      unsigned long long* f) {
#pragma unroll 4
    for (int k4 = 0; k4 < KH / 4; k4++) {
        ulonglong2 z = *(const ulonglong2*)(zrow + 4 * k4);
        ulonglong2 a = *(const ulonglong2*)(w1 + 4 * k4);
        ffma2(f[0], z.x, a.x); ffma2(f[1], z.y, a.y);
        ulonglong2 bq = *(const ulonglong2*)(w2 + 4 * k4);
        ffma2(f[2], z.x, bq.x); ffma2(f[3], z.y, bq.y);
        ulonglong2 cq = *(const ulonglong2*)(w3 + 4 * k4);
        ffma2(f[4], z.x, cq.x); ffma2(f[5], z.y, cq.y);
        ulonglong2 dq = *(const ulonglong2*)(w4 + 4 * k4);
        ffma2(f[6], z.x, dq.x); ffma2(f[7], z.y, dq.y);
    }
}

// --------------------------------- kernel ----------------------------------
__global__ void __launch_bounds__(NTHR, 1)
cfc_persistent_kernel(const float* __restrict__ x,   const float* __restrict__ ts,
                      const float* __restrict__ h0,  const float* __restrict__ s0,
                      const float* __restrict__ Wbb, const float* __restrict__ bbb,
                      const float* __restrict__ Wff1,const float* __restrict__ bff1,
                      const float* __restrict__ Wff2,const float* __restrict__ bff2,
                      const float* __restrict__ Wta, const float* __restrict__ bta,
                      const float* __restrict__ Wtb, const float* __restrict__ btb,
                      float* __restrict__ out) {
    extern __shared__ float smem[];
    float* s_wbb = smem;                        // [4][772]
    float* s_w4  = s_wbb + CPC * WBBP;          // [16][516]
    float* s_stg = s_w4  + 16 * W4P;            // [2][64][260]
    float* s_pA  = s_stg + 2 * STGF;            // [256]
    float* s_pB  = s_pA  + 256;                 // [256][5] (4 used)

    const int tid   = threadIdx.x;
    const int c     = tid & 3;
    const int b     = (tid >> 2) & 63;
    const int khalf = tid >> 8;                 // 0 or 1
    const int c0    = blockIdx.x * CPC;
    const int cg    = c0 + c;
    const int pid   = tid & 255;

    // ---- one-time: weight column slice -> SMEM (column-major, padded) ----
    for (int idx = tid; idx < ZC * CPC; idx += NTHR) {
        int k = idx >> 2, cc = idx & 3;
        s_wbb[cc * WBBP + k] = __ldg(Wbb + (size_t)k * Hc + c0 + cc);
    }
    {
        const float* Wm[4] = {Wff1, Wff2, Wta, Wtb};
#pragma unroll
        for (int m = 0; m < 4; m++) {
            for (int idx = tid; idx < Hc * CPC; idx += NTHR) {
                int k = idx >> 2, cc = idx & 3;
                s_w4[(m * 4 + cc) * W4P + k] = __ldg(Wm[m] + (size_t)k * Hc + c0 + cc);
            }
        }
    }
    const float bbbc = __ldg(bbb  + cg);
    const float bf1c = __ldg(bff1 + cg);
    const float bf2c = __ldg(bff2 + cg);
    const float btac = __ldg(bta  + cg);
    const float btbc = __ldg(btb  + cg);

    // ---- persistent per-thread state (khalf==0 owns it) ----
    float s_state = 0.0f;
    if (khalf == 0) {
        s_state = __ldg(s0 + b * Hc + cg);
        g_h[b * Hc + cg] = __ldg(h0 + b * Hc + cg);
    }

    unsigned sense0 = 0, ep = 0;
    if (tid == 0) {
        asm volatile("ld.acquire.gpu.u32 %0, [%1];"
                     : "=r"(sense0) : "l"(&g_sense) : "memory");
    }

    float* buf0 = s_stg;
    float* buf1 = s_stg + STGF;
    const float* wbp = s_wbb + c * WBBP;
    const float* w1p = s_w4 + (0 * 4 + c) * W4P;
    const float* w2p = s_w4 + (1 * 4 + c) * W4P;
    const float* w3p = s_w4 + (2 * 4 + c) * W4P;
    const float* w4p = s_w4 + (3 * 4 + c) * W4P;
    const float* zr  = (khalf ? buf0 : buf0);   // rebound per use
    const int rofs = b * ZPAD + khalf * KH;

    // initial barrier: h0 visible chip-wide; stage x(0) under the spin
    gbar_arrive(sense0, ep);
    stageA(buf0, x, 0, 0);           // outstanding: {x}
    gbar_wait(sense0, ep);

    for (int t = 0; t < Tc; t++) {
        // ============ Phase A: bb = silu(z @ Wbb + bbb) ============
        unsigned long long a0 = 0ull, a1 = 0ull;
        stageA(buf1, x, t, 256);                 // {x, h1}
        cp_wait<1>(); __syncthreads();
        gemmA(buf0 + rofs, wbp + 0   + khalf * KH, a0, a1);
        __syncthreads();
        stageA(buf0, x, t, 512);                 // {h1, h2}
        cp_wait<1>(); __syncthreads();
        gemmA(buf1 + rofs, wbp + 256 + khalf * KH, a0, a1);
        cp_wait<0>(); __syncthreads();
        gemmA(buf0 + rofs, wbp + 512 + khalf * KH, a0, a1);

        float apart = hsum2(a0) + hsum2(a1);
        if (khalf == 1) s_pA[pid] = apart;
        __syncthreads();
        if (khalf == 0) {
            float av  = apart + s_pA[pid] + bbbc;
            float bbv = av / (1.0f + expf(-av));
            g_bb[b * Hc + cg] = bbv;
        }
        gbar_arrive(sense0, ep);                 // bb barrier (arrive)
        // hide ts transcendental math under the spin
        float wts = 0.0f, tstv = 0.0f;
        if (khalf == 0) {
            tstv = __ldg(ts + b * Tc + t);
            float tn = 1.0f / tstv;
            wts = (tn > 0.0f) ? expf(tn * (1.0f - 2.0f * logf(tn))) : 0.0f;
        }
        gbar_wait(sense0, ep);

        // ====== Phase B: 4 GEMMs over bb; gate & update ======
        unsigned long long f[8] = {0ull,0ull,0ull,0ull,0ull,0ull,0ull,0ull};
        stageB(buf0, 0);                          // {b1}
        stageB(buf1, 256);                        // {b1, b2}
        cp_wait<1>(); __syncthreads();
        gemmB(buf0 + rofs, w1p + khalf * KH, w2p + khalf * KH,
              w3p + khalf * KH, w4p + khalf * KH, f);
        cp_wait<0>(); __syncthreads();
        gemmB(buf1 + rofs, w1p + 256 + khalf * KH, w2p + 256 + khalf * KH,
              w3p + 256 + khalf * KH, w4p + 256 + khalf * KH, f);

        float p1 = hsum2(f[0]) + hsum2(f[1]);
        float p2 = hsum2(f[2]) + hsum2(f[3]);
        float p3 = hsum2(f[4]) + hsum2(f[5]);
        float p4 = hsum2(f[6]) + hsum2(f[7]);
        if (khalf == 1) {
            float* pb = s_pB + pid * 5;
            pb[0] = p1; pb[1] = p2; pb[2] = p3; pb[3] = p4;
        }
        __syncthreads();
        if (khalf == 0) {
            const float* pb = s_pB + pid * 5;
            float ff1 = tanhf(p1 + pb[0] + bf1c);
            float ff2 = tanhf(p2 + pb[1] + bf2c);
            float tsum = (p3 + pb[2] + btac) * wts + (p4 + pb[3] + btbc);
            s_state += tsum;
            float ti = 1.0f / (1.0f + expf(-s_state));
            float hn = ff1 + ti * (ff2 - ff1);
            g_h[b * Hc + cg] = hn;
            out[((size_t)b * Tc + t) * Hc + cg] = hn;
        }
        gbar_arrive(sense0, ep);                 // h barrier (arrive)
        if (t + 1 < Tc) stageA(buf0, x, t + 1, 0);   // prefetch x under spin
        else            cp_commit();                  // keep group count aligned
        gbar_wait(sense0, ep);
    }
    (void)zr;
}

// --------------------------------- launch ----------------------------------
extern "C" void kernel_launch(void* const* d_in, const int* in_sizes, int n_in,
                              void* d_out, int out_size) {
    (void)in_sizes; (void)n_in; (void)out_size;
    cudaFuncSetAttribute(cfc_persistent_kernel,
                         cudaFuncAttributeMaxDynamicSharedMemorySize, SMEM_BYTES);
    cfc_persistent_kernel<<<NCTA, NTHR, SMEM_BYTES>>>(
        (const float*)d_in[0],  (const float*)d_in[1],
        (const float*)d_in[2],  (const float*)d_in[3],
        (const float*)d_in[4],  (const float*)d_in[5],
        (const float*)d_in[6],  (const float*)d_in[7],
        (const float*)d_in[8],  (const float*)d_in[9],
        (const float*)d_in[10], (const float*)d_in[11],
        (const float*)d_in[12], (const float*)d_in[13],
        (float*)d_out);
}

// round 8
// speedup vs baseline: 1.3976x; 1.3695x over previous
#include <cuda_runtime.h>
#include <cuda_bf16.h>
#include <math.h>

// ---------------------------------------------------------------------------
// CfC recurrence v3: persistent weight-stationary kernel with 4x4 register
// tiles (16 MACs per 2x LDS.128), k-major activation staging, bank-skewed
// SMEM layouts, cp.async 3-buffer ring, shuffle k-reductions.
// B=64, T=1024, D=256, H=512, BU=512, Z=768.  128 CTAs x 256 threads,
// CTA owns 4 H-columns of all 5 weight matrices.
// ---------------------------------------------------------------------------

#define Bc   64
#define Tc   1024
#define Dc   256
#define Hc   512
#define ZC   768
#define NCTA 128
#define NTHR 256
#define ZROW 96                        // staged z row stride (floats)
#define ZBUF (128 * ZROW)              // one chunk buffer: 128 rows
#define WA_SEC 196                     // Wbb per-ks2 section stride
#define WB_SEC 2056                    // W4 per-km section stride
#define SMEM_FLOATS (16*WA_SEC + 4*WB_SEC + 3*ZBUF + 256 + 1024)
#define SMEM_BYTES  (SMEM_FLOATS * 4)

// -------------------- device-global state ----------------------------------
__device__ unsigned g_count = 0;
__device__ unsigned g_sense = 0;
__device__ __align__(256) float g_h [Hc * Bc];    // column-major [col][b]
__device__ __align__(256) float g_bb[Hc * Bc];    // column-major [col][b]
__device__ __align__(256) float g_xT[(size_t)Tc * Dc * Bc];   // [t][d][b]

// ------------------------------- helpers -----------------------------------
__device__ __forceinline__ void cp16(float* dst_smem, const float* src_gmem) {
    unsigned d = (unsigned)__cvta_generic_to_shared(dst_smem);
    asm volatile("cp.async.cg.shared.global [%0], [%1], 16;"
                 :: "r"(d), "l"(src_gmem) : "memory");
}
__device__ __forceinline__ void cp_commit() {
    asm volatile("cp.async.commit_group;" ::: "memory");
}
template <int N>
__device__ __forceinline__ void cp_wait() {
    asm volatile("cp.async.wait_group %0;" :: "n"(N) : "memory");
}

__device__ __forceinline__ void ffma2(unsigned long long& d,
                                      unsigned long long a,
                                      unsigned long long b) {
    asm("fma.rn.f32x2 %0, %1, %2, %0;" : "+l"(d) : "l"(a), "l"(b));
}
__device__ __forceinline__ void add2(unsigned long long& d,
                                     unsigned long long a,
                                     unsigned long long b) {
    asm("add.rn.f32x2 %0, %1, %2;" : "=l"(d) : "l"(a), "l"(b));
}
__device__ __forceinline__ unsigned long long dup2(float v) {
    unsigned long long r; unsigned u = __float_as_uint(v);
    asm("mov.b64 %0, {%1, %1};" : "=l"(r) : "r"(u));
    return r;
}
__device__ __forceinline__ float lo2(unsigned long long v) {
    return __uint_as_float((unsigned)v);
}
__device__ __forceinline__ float hi2(unsigned long long v) {
    return __uint_as_float((unsigned)(v >> 32));
}

// 4 rows x 4 cols outer product: z = 4 rows, w = 4 cols (as 2 packed pairs).
__device__ __forceinline__ void mac16(unsigned long long* acc, float4 z,
                                      ulonglong2 w) {
    unsigned long long zz;
    zz = dup2(z.x); ffma2(acc[0], zz, w.x); ffma2(acc[1], zz, w.y);
    zz = dup2(z.y); ffma2(acc[2], zz, w.x); ffma2(acc[3], zz, w.y);
    zz = dup2(z.z); ffma2(acc[4], zz, w.x); ffma2(acc[5], zz, w.y);
    zz = dup2(z.w); ffma2(acc[6], zz, w.x); ffma2(acc[7], zz, w.y);
}

// ---- split global barrier (sense-reversing epoch) ----
__device__ __forceinline__ void gbar_arrive(unsigned sense0, unsigned& ep) {
    __syncthreads();
    ep++;
    if (threadIdx.x == 0) {
        __threadfence();
        if (atomicAdd(&g_count, 1u) == (unsigned)(NCTA - 1)) {
            atomicExch(&g_count, 0u);
            asm volatile("st.release.gpu.u32 [%0], %1;"
                         :: "l"(&g_sense), "r"(sense0 + ep) : "memory");
        }
    }
}
__device__ __forceinline__ void gbar_wait(unsigned sense0, unsigned ep) {
    if (threadIdx.x == 0) {
        unsigned v, target = sense0 + ep;
        do {
            asm volatile("ld.acquire.gpu.u32 %0, [%1];"
                         : "=r"(v) : "l"(&g_sense) : "memory");
        } while (v != target);
    }
    __syncthreads();
}

// Stage one 128-row k-chunk (rows of 64 floats) into a skewed SMEM buffer.
__device__ __forceinline__ void stage_chunk(float* buf,
                                            const float* __restrict__ src) {
    int tid = threadIdx.x;
#pragma unroll
    for (int i = 0; i < 8; i++) {
        int lin = tid + i * NTHR;           // 0..2047
        int l   = lin >> 4;                 // row 0..127
        int b4  = (lin & 15) << 2;          // float4 col
        cp16(buf + l * ZROW + (((l >> 3) & 7) << 2) + b4,
             src + l * Bc + b4);
    }
    cp_commit();
}

// Phase A: one chunk (8 k per thread), 4x4 tile.
__device__ __forceinline__ void gemmA_chunk(const float* __restrict__ buf,
                                            const float* __restrict__ wsec,
                                            int ks2, int rgA,
                                            unsigned long long* acc) {
    const float* zp = buf + (ks2 * 8) * ZROW + ((ks2 & 7) << 2) + (rgA << 2);
#pragma unroll
    for (int i = 0; i < 8; i++) {
        float4 z = *(const float4*)(zp + i * ZROW);
        ulonglong2 w = *(const ulonglong2*)(wsec + i * 4);
        mac16(acc, z, w);
    }
}

// Phase B: one chunk (32 k per thread), 4x4 tile (one matrix's 4 cols).
__device__ __forceinline__ void gemmB_chunk(const float* __restrict__ buf,
                                            const float* __restrict__ wsec,
                                            int km, int rgB,
                                            unsigned long long* acc) {
    const float* zb = buf + (km * 32) * ZROW + (rgB << 2);
#pragma unroll
    for (int j = 0; j < 4; j++) {
        const float* zp = zb + (j * 8) * ZROW + ((((km << 2) + j) & 7) << 2);
        const float* wp = wsec + j * 128;
#pragma unroll
        for (int i = 0; i < 8; i++) {
            float4 z = *(const float4*)(zp + i * ZROW);
            ulonglong2 w = *(const ulonglong2*)(wp + i * 16);
            mac16(acc, z, w);
        }
    }
}

// ------------------------- x transpose kernel ------------------------------
__global__ void __launch_bounds__(256) xpose_kernel(const float* __restrict__ x) {
    __shared__ float tile[32 * 65];
    int t = blockIdx.x;
    int tid = threadIdx.x;
    for (int dblk = 0; dblk < 8; dblk++) {
        int dl = tid & 31, bq = tid >> 5;
#pragma unroll
        for (int b8 = 0; b8 < 8; b8++) {
            int b = bq * 8 + b8;
            tile[dl * 65 + b] = x[((size_t)b * Tc + t) * Dc + dblk * 32 + dl];
        }
        __syncthreads();
        int b = tid & 63, dq = tid >> 6;
#pragma unroll
        for (int j = 0; j < 8; j++) {
            int d = dq * 8 + j;
            g_xT[((size_t)t * Dc + dblk * 32 + d) * Bc + b] = tile[d * 65 + b];
        }
        __syncthreads();
    }
}

// --------------------------------- kernel ----------------------------------
__global__ void __launch_bounds__(NTHR, 1)
cfc_persistent_kernel(const float* __restrict__ ts,
                      const float* __restrict__ h0,  const float* __restrict__ s0,
                      const float* __restrict__ Wbb, const float* __restrict__ bbb,
                      const float* __restrict__ Wff1,const float* __restrict__ bff1,
                      const float* __restrict__ Wff2,const float* __restrict__ bff2,
                      const float* __restrict__ Wta, const float* __restrict__ bta,
                      const float* __restrict__ Wtb, const float* __restrict__ btb,
                      float* __restrict__ out) {
    extern __shared__ float smem[];
    float* s_wA   = smem;                       // 16 sections x 196
    float* s_wB   = s_wA + 16 * WA_SEC;         // 4 sections x 2056
    float* s_z0   = s_wB + 4 * WB_SEC;          // 3 x ZBUF
    float* s_redA = s_z0 + 3 * ZBUF;            // 256
    float* s_redB = s_redA + 256;               // 1024

    const int tid = threadIdx.x;
    const int c0  = blockIdx.x * 4;
    // phase A ids
    const int ks2 = tid & 15, rgA = tid >> 4;
    // phase B ids
    const int km = tid & 3, rgB = (tid >> 2) & 15, mB = tid >> 6;
    // epilogue ids
    const int ec = tid & 3, eb = tid >> 2;
    const int cg = c0 + ec;
    const int eidx = ((eb >> 2) << 4) + ((eb & 3) << 2) + ec;

    // ---- one-time: weights -> sectioned SMEM ----
    for (int idx = tid; idx < ZC * 4; idx += NTHR) {
        int k = idx >> 2, cc = idx & 3;
        int sec = (k & 127) >> 3, ch = k >> 7, i = k & 7;
        s_wA[sec * WA_SEC + (ch * 8 + i) * 4 + cc] =
            __ldg(Wbb + (size_t)k * Hc + c0 + cc);
    }
    {
        const float* Wm[4] = {Wff1, Wff2, Wta, Wtb};
#pragma unroll
        for (int m = 0; m < 4; m++)
            for (int idx = tid; idx < Hc * 4; idx += NTHR) {
                int k = idx >> 2, cc = idx & 3;
                int sec = (k & 127) >> 5, ch = k >> 7, i = k & 31;
                s_wB[sec * WB_SEC + (ch * 32 + i) * 16 + m * 4 + cc] =
                    __ldg(Wm[m] + (size_t)k * Hc + c0 + cc);
            }
    }
    const float bbbc = __ldg(bbb  + cg);
    const float bf1c = __ldg(bff1 + cg);
    const float bf2c = __ldg(bff2 + cg);
    const float btac = __ldg(bta  + cg);
    const float btbc = __ldg(btb  + cg);

    float s_state = __ldg(s0 + (size_t)eb * Hc + cg);
    g_h[cg * Bc + eb] = __ldg(h0 + (size_t)eb * Hc + cg);

    unsigned sense0 = 0, ep = 0;
    if (tid == 0) {
        asm volatile("ld.acquire.gpu.u32 %0, [%1];"
                     : "=r"(sense0) : "l"(&g_sense) : "memory");
    }

    float* zb[3] = {s_z0, s_z0 + ZBUF, s_z0 + 2 * ZBUF};

    gbar_arrive(sense0, ep);                    // publish h0
    stage_chunk(zb[0], g_xT);                   // t=0 chunk 0 (x)
    stage_chunk(zb[1], g_xT + (size_t)128 * Bc);// t=0 chunk 1 (x)
    gbar_wait(sense0, ep);

    for (int t = 0; t < Tc; t++) {
        // ============ Phase A: bb = silu(z @ Wbb + bbb), K=768 ============
        unsigned long long acc[8] = {0,0,0,0,0,0,0,0};
#pragma unroll
        for (int c = 0; c < 6; c++) {
            if (c + 2 < 6) {
                int cn = c + 2;
                const float* src = (cn < 2)
                    ? g_xT + ((size_t)t * Dc + cn * 128) * Bc
                    : g_h + (size_t)(cn * 128 - 256) * Bc;
                stage_chunk(zb[cn % 3], src);
            }
            if (c <= 3)      cp_wait<2>();
            else if (c == 4) cp_wait<1>();
            else             cp_wait<0>();
            __syncthreads();
            gemmA_chunk(zb[c % 3], s_wA + ks2 * WA_SEC + c * 32, ks2, rgA, acc);
            __syncthreads();
        }
        // reduce over 16-way ksplit (lane bits 0..3)
#pragma unroll
        for (int d = 1; d <= 8; d <<= 1)
#pragma unroll
            for (int q = 0; q < 8; q++) {
                unsigned long long o = __shfl_xor_sync(0xffffffffu, acc[q], d);
                add2(acc[q], acc[q], o);
            }
        if ((tid & 15) == 0) {
            float* dst = s_redA + rgA * 16;
#pragma unroll
            for (int r = 0; r < 4; r++) {
                float4 v = make_float4(lo2(acc[2*r]), hi2(acc[2*r]),
                                       lo2(acc[2*r+1]), hi2(acc[2*r+1]));
                *(float4*)(dst + r * 4) = v;
            }
        }
        __syncthreads();
        {
            float av  = s_redA[eidx] + bbbc;
            float bbv = av / (1.0f + expf(-av));       // silu
            g_bb[cg * Bc + eb] = bbv;
        }
        gbar_arrive(sense0, ep);                        // bb barrier
        float tstv = __ldg(ts + (size_t)eb * Tc + t);   // hidden under spin
        float tn   = 1.0f / tstv;
        float wts  = (tn > 0.0f) ? expf(tn * (1.0f - 2.0f * logf(tn))) : 0.0f;
        gbar_wait(sense0, ep);

        // ====== Phase B: 4 GEMMs over bb (K=512); gate & update ======
        unsigned long long fac[8] = {0,0,0,0,0,0,0,0};
        stage_chunk(zb[0], g_bb);
        stage_chunk(zb[1], g_bb + (size_t)128 * Bc);
#pragma unroll
        for (int c = 0; c < 4; c++) {
            if (c + 2 < 4)
                stage_chunk(zb[(c + 2) % 3], g_bb + (size_t)(c + 2) * 128 * Bc);
            if (c <= 1)      cp_wait<2>();
            else if (c == 2) cp_wait<1>();
            else             cp_wait<0>();
            __syncthreads();
            gemmB_chunk(zb[c % 3],
                        s_wB + km * WB_SEC + c * 512 + mB * 4, km, rgB, fac);
            __syncthreads();
        }
        // reduce over 4-way ksplit (lane bits 0..1)
#pragma unroll
        for (int d = 1; d <= 2; d <<= 1)
#pragma unroll
            for (int q = 0; q < 8; q++) {
                unsigned long long o = __shfl_xor_sync(0xffffffffu, fac[q], d);
                add2(fac[q], fac[q], o);
            }
        if ((tid & 3) == 0) {
            float* dst = s_redB + mB * 256 + rgB * 16;
#pragma unroll
            for (int r = 0; r < 4; r++) {
                float4 v = make_float4(lo2(fac[2*r]), hi2(fac[2*r]),
                                       lo2(fac[2*r+1]), hi2(fac[2*r+1]));
                *(float4*)(dst + r * 4) = v;
            }
        }
        __syncthreads();
        {
            float p0 = s_redB[0 * 256 + eidx];
            float p1 = s_redB[1 * 256 + eidx];
            float p2 = s_redB[2 * 256 + eidx];
            float p3 = s_redB[3 * 256 + eidx];
            float ff1 = tanhf(p0 + bf1c);
            float ff2 = tanhf(p1 + bf2c);
            s_state += (p2 + btac) * wts + (p3 + btbc);
            float ti = 1.0f / (1.0f + expf(-s_state));
            float hn = ff1 + ti * (ff2 - ff1);
            g_h[cg * Bc + eb] = hn;
            out[((size_t)eb * Tc + t) * Hc + cg] = hn;
        }
        gbar_arrive(sense0, ep);                        // h barrier
        if (t + 1 < Tc) {                               // prefetch next x
            stage_chunk(zb[0], g_xT + ((size_t)(t + 1) * Dc) * Bc);
            stage_chunk(zb[1], g_xT + ((size_t)(t + 1) * Dc + 128) * Bc);
        }
        gbar_wait(sense0, ep);
    }
    cp_wait<0>();
}

// --------------------------------- launch ----------------------------------
extern "C" void kernel_launch(void* const* d_in, const int* in_sizes, int n_in,
                              void* d_out, int out_size) {
    (void)in_sizes; (void)n_in; (void)out_size;
    cudaFuncSetAttribute(cfc_persistent_kernel,
                         cudaFuncAttributeMaxDynamicSharedMemorySize, SMEM_BYTES);
    xpose_kernel<<<Tc, 256>>>((const float*)d_in[0]);
    cfc_persistent_kernel<<<NCTA, NTHR, SMEM_BYTES>>>(
        (const float*)d_in[1],
        (const float*)d_in[2],  (const float*)d_in[3],
        (const float*)d_in[4],  (const float*)d_in[5],
        (const float*)d_in[6],  (const float*)d_in[7],
        (const float*)d_in[8],  (const float*)d_in[9],
        (const float*)d_in[10], (const float*)d_in[11],
        (const float*)d_in[12], (const float*)d_in[13],
        (float*)d_out);
}